// round 7
// baseline (speedup 1.0000x reference)
#include <cuda_runtime.h>
#include <cstdint>

#define T_DIM 2048
#define H_DIM 1024
#define I_DIM 1408
#define E_DIM 8
#define K_TOP 2
#define CAP   1024
#define TWO_I 2816

#define BK    32
#define LDA   36
#define TILE_F (128 * LDA)
#define STAGE_F (2 * TILE_F)

// ---------------- scratch (device globals) ----------------------------------
__device__ int   d_pos[T_DIM * K_TOP];
__device__ int   d_cnt[E_DIM];
__device__ int   d_slot[E_DIM * CAP];                       // (e,pos) -> flat slot
__device__ float d_h[(size_t)E_DIM * CAP * TWO_I];          // pre-activation, 92 MB
__device__ float d_y[(size_t)E_DIM * CAP * H_DIM];          // expert output, 33 MB

// ---------------- helpers ---------------------------------------------------
__device__ __forceinline__ unsigned f2tf32(float x) {
    unsigned r;
    asm("cvt.rna.tf32.f32 %0, %1;" : "=r"(r) : "f"(x));
    return r;
}

__device__ __forceinline__ void mma_tf32(float* c, const unsigned* a, const unsigned* b) {
    asm volatile(
        "mma.sync.aligned.m16n8k8.row.col.f32.tf32.tf32.f32 "
        "{%0,%1,%2,%3}, {%4,%5,%6,%7}, {%8,%9}, {%0,%1,%2,%3};"
        : "+f"(c[0]), "+f"(c[1]), "+f"(c[2]), "+f"(c[3])
        : "r"(a[0]), "r"(a[1]), "r"(a[2]), "r"(a[3]),
          "r"(b[0]), "r"(b[1]));
}

__device__ __forceinline__ uint4 cvt4(float4 v) {
    uint4 w;
    w.x = f2tf32(v.x); w.y = f2tf32(v.y); w.z = f2tf32(v.z); w.w = f2tf32(v.w);
    return w;
}

// 16 MMAs covering one k8 step for this warp
__device__ __forceinline__ void compute8(const float* __restrict__ A,
                                         const float* __restrict__ B,
                                         int kk, int wm, int wn, int g, int t,
                                         float acc[4][4][4]) {
    unsigned a[4][4], b[4][2];
#pragma unroll
    for (int mf = 0; mf < 4; mf++) {
        int r = wm * 64 + mf * 16;
        a[mf][0] = __float_as_uint(A[(r + g) * LDA + kk + t]);
        a[mf][1] = __float_as_uint(A[(r + g + 8) * LDA + kk + t]);
        a[mf][2] = __float_as_uint(A[(r + g) * LDA + kk + t + 4]);
        a[mf][3] = __float_as_uint(A[(r + g + 8) * LDA + kk + t + 4]);
    }
#pragma unroll
    for (int nf = 0; nf < 4; nf++) {
        int r = wn * 32 + nf * 8;
        b[nf][0] = __float_as_uint(B[(r + g) * LDA + kk + t]);
        b[nf][1] = __float_as_uint(B[(r + g) * LDA + kk + t + 4]);
    }
#pragma unroll
    for (int mf = 0; mf < 4; mf++)
#pragma unroll
        for (int nf = 0; nf < 4; nf++) mma_tf32(acc[mf][nf], a[mf], b[nf]);
}

// ---------------- 1. routing ------------------------------------------------
__global__ void route_kernel(const int* __restrict__ ids) {
    __shared__ int s_cnt[256][8];
    int tid = threadIdx.x;
    int local[8];
#pragma unroll
    for (int e = 0; e < 8; e++) local[e] = 0;
    int base = tid * 16;
#pragma unroll
    for (int i = 0; i < 16; i++) {
        int e = ids[base + i];
#pragma unroll
        for (int q = 0; q < 8; q++) if (q == e) local[q]++;
    }
#pragma unroll
    for (int e = 0; e < 8; e++) s_cnt[tid][e] = local[e];
    __syncthreads();
    if (tid < 8) {
        int acc = 0;
        for (int i = 0; i < 256; i++) {
            int v = s_cnt[i][tid];
            s_cnt[i][tid] = acc;
            acc += v;
        }
        d_cnt[tid] = acc;
    }
    __syncthreads();
    int run[8];
#pragma unroll
    for (int e = 0; e < 8; e++) run[e] = s_cnt[tid][e];
    for (int i = 0; i < 16; i++) {
        int idx = base + i;
        int e = ids[idx];
        int p = 0;
#pragma unroll
        for (int q = 0; q < 8; q++) if (q == e) p = run[q]++;
        d_pos[idx] = p;
        if (p < CAP) d_slot[e * CAP + p] = idx;
    }
}

// ---------------- 2. GEMM1: h = gather(x) @ w1^T ----------------------------
// BM=128 BN=128 BK=32, double-buffered smem, software pipeline, 2 CTA/SM.
__global__ __launch_bounds__(256, 2) void gemm1_kernel(const float* __restrict__ hidden,
                                                       const float* __restrict__ w1) {
    const int e = blockIdx.z, nt = blockIdx.y, mt = blockIdx.x;
    const int cnt = min(d_cnt[e], CAP);
    const int m0 = mt * 128;
    if (m0 >= cnt) return;

    extern __shared__ float sm[];

    const int tid = threadIdx.x;
    const int lane = tid & 31, warp = tid >> 5;
    const int wm = warp & 1, wn = warp >> 1;
    const int g = lane >> 2, t = lane & 3;

    float acc[4][4][4];
#pragma unroll
    for (int mf = 0; mf < 4; mf++)
#pragma unroll
        for (int nf = 0; nf < 4; nf++)
#pragma unroll
            for (int q = 0; q < 4; q++) acc[mf][nf][q] = 0.f;

    // loader: thread covers rows r0, r0+64 at 4-float column c0 within a 16-col half
    const int r0 = tid >> 2;
    const int c0 = (tid & 3) * 4;
    int atok[2]; bool aval[2];
#pragma unroll
    for (int i = 0; i < 2; i++) {
        int m = m0 + r0 + i * 64;
        aval[i] = (m < cnt);
        atok[i] = aval[i] ? (d_slot[e * CAP + m] >> 1) : 0;
    }
    const float* apart0 = hidden + (size_t)atok[0] * H_DIM + c0;
    const float* apart1 = hidden + (size_t)atok[1] * H_DIM + c0;
    const float* bpart0 = w1 + ((size_t)e * TWO_I + nt * 128 + r0) * H_DIM + c0;
    const float* bpart1 = bpart0 + (size_t)64 * H_DIM;

    float4 ra0, ra1, rb0, rb1;

#define G1_LDG(col) do {                                                         \
    ra0 = aval[0] ? *(const float4*)(apart0 + (col)) : make_float4(0,0,0,0);     \
    ra1 = aval[1] ? *(const float4*)(apart1 + (col)) : make_float4(0,0,0,0);     \
    rb0 = *(const float4*)(bpart0 + (col));                                      \
    rb1 = *(const float4*)(bpart1 + (col));                                      \
} while (0)

#define G1_STS(stage, halfcol) do {                                              \
    float* A_ = sm + (stage) * STAGE_F;                                          \
    float* B_ = A_ + TILE_F;                                                     \
    *(uint4*)(A_ + r0 * LDA + (halfcol) + c0) = cvt4(ra0);                       \
    *(uint4*)(A_ + (r0 + 64) * LDA + (halfcol) + c0) = cvt4(ra1);                \
    *(uint4*)(B_ + r0 * LDA + (halfcol) + c0) = cvt4(rb0);                       \
    *(uint4*)(B_ + (r0 + 64) * LDA + (halfcol) + c0) = cvt4(rb1);                \
} while (0)

    // prologue: chunk 0 -> stage 0
    G1_LDG(0);  G1_STS(0, 0);
    G1_LDG(16); G1_STS(0, 16);
    __syncthreads();

    const int NC = H_DIM / BK;  // 32
    for (int c = 0; c < NC; c++) {
        const int s = c & 1;
        const float* A = sm + s * STAGE_F;
        const float* B = A + TILE_F;
        const bool more = (c + 1 < NC);
        const int kn = (c + 1) * BK;

        if (more) G1_LDG(kn);
        compute8(A, B, 0, wm, wn, g, t, acc);
        compute8(A, B, 8, wm, wn, g, t, acc);
        if (more) G1_STS(s ^ 1, 0);
        if (more) G1_LDG(kn + 16);
        compute8(A, B, 16, wm, wn, g, t, acc);
        compute8(A, B, 24, wm, wn, g, t, acc);
        if (more) G1_STS(s ^ 1, 16);
        __syncthreads();
    }

    // epilogue -> d_h (fp32)
#pragma unroll
    for (int mf = 0; mf < 4; mf++) {
        int mlo = m0 + wm * 64 + mf * 16 + g;
        int mhi = mlo + 8;
#pragma unroll
        for (int nf = 0; nf < 4; nf++) {
            int col = nt * 128 + wn * 32 + nf * 8 + 2 * t;
            if (mlo < cnt) {
                float* dst = d_h + ((size_t)e * CAP + mlo) * TWO_I + col;
                dst[0] = acc[mf][nf][0];
                dst[1] = acc[mf][nf][1];
            }
            if (mhi < cnt) {
                float* dst = d_h + ((size_t)e * CAP + mhi) * TWO_I + col;
                dst[0] = acc[mf][nf][2];
                dst[1] = acc[mf][nf][3];
            }
        }
    }
#undef G1_LDG
#undef G1_STS
}

// ---------------- 3. GEMM2: y = (silu(gate)*up) @ w2^T ----------------------
__global__ __launch_bounds__(256, 2) void gemm2_kernel(const float* __restrict__ w2) {
    const int e = blockIdx.z, nt = blockIdx.y, mt = blockIdx.x;
    const int cnt = min(d_cnt[e], CAP);
    const int m0 = mt * 128;
    if (m0 >= cnt) return;

    extern __shared__ float sm[];

    const int tid = threadIdx.x;
    const int lane = tid & 31, warp = tid >> 5;
    const int wm = warp & 1, wn = warp >> 1;
    const int g = lane >> 2, t = lane & 3;

    float acc[4][4][4];
#pragma unroll
    for (int mf = 0; mf < 4; mf++)
#pragma unroll
        for (int nf = 0; nf < 4; nf++)
#pragma unroll
            for (int q = 0; q < 4; q++) acc[mf][nf][q] = 0.f;

    const int r0 = tid >> 2;
    const int c0 = (tid & 3) * 4;
    bool aval[2];
    aval[0] = (m0 + r0 < cnt);
    aval[1] = (m0 + r0 + 64 < cnt);
    const float* hrow0 = d_h + ((size_t)e * CAP + m0 + r0) * TWO_I + c0;
    const float* hrow1 = hrow0 + (size_t)64 * TWO_I;
    const float* bpart0 = w2 + ((size_t)e * H_DIM + nt * 128 + r0) * I_DIM + c0;
    const float* bpart1 = bpart0 + (size_t)64 * I_DIM;

    float4 rg0, rg1, ru0, ru1, rb0, rb1;

#define SILU4(gv, uv) make_float4(                              \
    (gv).x * (uv).x / (1.f + __expf(-(gv).x)),                  \
    (gv).y * (uv).y / (1.f + __expf(-(gv).y)),                  \
    (gv).z * (uv).z / (1.f + __expf(-(gv).z)),                  \
    (gv).w * (uv).w / (1.f + __expf(-(gv).w)))

#define G2_LDG(col) do {                                                           \
    if (aval[0]) { rg0 = *(const float4*)(hrow0 + (col));                          \
                   ru0 = *(const float4*)(hrow0 + (col) + I_DIM); }                \
    else { rg0 = make_float4(0,0,0,0); ru0 = rg0; }                                \
    if (aval[1]) { rg1 = *(const float4*)(hrow1 + (col));                          \
                   ru1 = *(const float4*)(hrow1 + (col) + I_DIM); }                \
    else { rg1 = make_float4(0,0,0,0); ru1 = rg1; }                                \
    rb0 = *(const float4*)(bpart0 + (col));                                        \
    rb1 = *(const float4*)(bpart1 + (col));                                        \
} while (0)

#define G2_STS(stage, halfcol) do {                                                \
    float* A_ = sm + (stage) * STAGE_F;                                            \
    float* B_ = A_ + TILE_F;                                                       \
    *(uint4*)(A_ + r0 * LDA + (halfcol) + c0) = cvt4(SILU4(rg0, ru0));             \
    *(uint4*)(A_ + (r0 + 64) * LDA + (halfcol) + c0) = cvt4(SILU4(rg1, ru1));      \
    *(uint4*)(B_ + r0 * LDA + (halfcol) + c0) = cvt4(rb0);                         \
    *(uint4*)(B_ + (r0 + 64) * LDA + (halfcol) + c0) = cvt4(rb1);                  \
} while (0)

    G2_LDG(0);  G2_STS(0, 0);
    G2_LDG(16); G2_STS(0, 16);
    __syncthreads();

    const int NC = I_DIM / BK;  // 44
    for (int c = 0; c < NC; c++) {
        const int s = c & 1;
        const float* A = sm + s * STAGE_F;
        const float* B = A + TILE_F;
        const bool more = (c + 1 < NC);
        const int kn = (c + 1) * BK;

        if (more) G2_LDG(kn);
        compute8(A, B, 0, wm, wn, g, t, acc);
        compute8(A, B, 8, wm, wn, g, t, acc);
        if (more) G2_STS(s ^ 1, 0);
        if (more) G2_LDG(kn + 16);
        compute8(A, B, 16, wm, wn, g, t, acc);
        compute8(A, B, 24, wm, wn, g, t, acc);
        if (more) G2_STS(s ^ 1, 16);
        __syncthreads();
    }

#pragma unroll
    for (int mf = 0; mf < 4; mf++) {
        int mlo = m0 + wm * 64 + mf * 16 + g;
        int mhi = mlo + 8;
#pragma unroll
        for (int nf = 0; nf < 4; nf++) {
            int col = nt * 128 + wn * 32 + nf * 8 + 2 * t;
            if (mlo < cnt) {
                float* dst = d_y + ((size_t)e * CAP + mlo) * H_DIM + col;
                dst[0] = acc[mf][nf][0];
                dst[1] = acc[mf][nf][1];
            }
            if (mhi < cnt) {
                float* dst = d_y + ((size_t)e * CAP + mhi) * H_DIM + col;
                dst[0] = acc[mf][nf][2];
                dst[1] = acc[mf][nf][3];
            }
        }
    }
#undef G2_LDG
#undef G2_STS
}

// ---------------- 4. combine ------------------------------------------------
__global__ void combine_kernel(const float* __restrict__ tw,
                               const int* __restrict__ ids,
                               float* __restrict__ out) {
    int tok = blockIdx.x;
    int e0 = ids[tok * 2 + 0], e1 = ids[tok * 2 + 1];
    int p0 = d_pos[tok * 2 + 0], p1 = d_pos[tok * 2 + 1];
    float w0 = tw[tok * 2 + 0], w1v = tw[tok * 2 + 1];
    bool k0 = (p0 < CAP), k1 = (p1 < CAP);

    int c = threadIdx.x;
    float4 r = make_float4(0.f, 0.f, 0.f, 0.f);
    if (k0) {
        float4 v = *(const float4*)(d_y + ((size_t)e0 * CAP + p0) * H_DIM + c * 4);
        r.x += w0 * v.x; r.y += w0 * v.y; r.z += w0 * v.z; r.w += w0 * v.w;
    }
    if (k1) {
        float4 v = *(const float4*)(d_y + ((size_t)e1 * CAP + p1) * H_DIM + c * 4);
        r.x += w1v * v.x; r.y += w1v * v.y; r.z += w1v * v.z; r.w += w1v * v.w;
    }
    *(float4*)(out + (size_t)tok * H_DIM + c * 4) = r;
}

// ---------------- launch -----------------------------------------------------
extern "C" void kernel_launch(void* const* d_in, const int* in_sizes, int n_in,
                              void* d_out, int out_size) {
    const float* hidden = (const float*)d_in[0];
    const float* w1     = (const float*)d_in[1];
    const float* w2     = (const float*)d_in[2];
    const float* tw     = (const float*)d_in[3];
    const int*   ids    = (const int*)d_in[4];
    float* out = (float*)d_out;

    const int smem = 2 * STAGE_F * (int)sizeof(float);  // 73728
    cudaFuncSetAttribute(gemm1_kernel, cudaFuncAttributeMaxDynamicSharedMemorySize, smem);
    cudaFuncSetAttribute(gemm2_kernel, cudaFuncAttributeMaxDynamicSharedMemorySize, smem);

    route_kernel<<<1, 256>>>(ids);
    gemm1_kernel<<<dim3(CAP / 128, TWO_I / 128, E_DIM), 256, smem>>>(hidden, w1);
    gemm2_kernel<<<dim3(CAP / 128, H_DIM / 128, E_DIM), 256, smem>>>(w2);
    combine_kernel<<<T_DIM, 256>>>(tw, ids, out);
}

// round 8
// speedup vs baseline: 1.3087x; 1.3087x over previous
#include <cuda_runtime.h>
#include <cuda_fp16.h>
#include <cstdint>

#define T_DIM 2048
#define H_DIM 1024
#define I_DIM 1408
#define E_DIM 8
#define K_TOP 2
#define CAP   1024
#define TWO_I 2816
#define BKH   64      // K elements per chunk (64 halves = 128B rows)

// ---------------- scratch (device globals) ----------------------------------
__device__ int    d_pos[T_DIM * K_TOP];
__device__ int    d_cnt[E_DIM];
__device__ int    d_slot[E_DIM * CAP];
__device__ __half d_act[(size_t)E_DIM * CAP * I_DIM];   // silu(gate)*up, fp16, 23MB
__device__ float  d_y[(size_t)E_DIM * CAP * H_DIM];     // expert output, 33MB

// ---------------- helpers ---------------------------------------------------
__device__ __forceinline__ uint32_t smem_u32(const void* p) {
    uint32_t a;
    asm("{ .reg .u64 t; cvta.to.shared.u64 t, %1; cvt.u32.u64 %0, t; }" : "=r"(a) : "l"(p));
    return a;
}
// pack two fp32 -> f16x2 (lo in low half)
__device__ __forceinline__ uint32_t cvt2h(float lo, float hi) {
    uint32_t r;
    asm("cvt.rn.f16x2.f32 %0, %1, %2;" : "=r"(r) : "f"(hi), "f"(lo));
    return r;
}
__device__ __forceinline__ uint4 pack8(float4 x, float4 y) {
    uint4 u;
    u.x = cvt2h(x.x, x.y); u.y = cvt2h(x.z, x.w);
    u.z = cvt2h(y.x, y.y); u.w = cvt2h(y.z, y.w);
    return u;
}
__device__ __forceinline__ void ldsm4(uint32_t& r0, uint32_t& r1, uint32_t& r2, uint32_t& r3,
                                      uint32_t addr) {
    asm volatile("ldmatrix.sync.aligned.m8n8.x4.shared.b16 {%0,%1,%2,%3}, [%4];"
        : "=r"(r0), "=r"(r1), "=r"(r2), "=r"(r3) : "r"(addr));
}
__device__ __forceinline__ void mma_f16(float* c, const uint32_t* a, const uint32_t* b) {
    asm volatile("mma.sync.aligned.m16n8k16.row.col.f32.f16.f16.f32 "
        "{%0,%1,%2,%3}, {%4,%5,%6,%7}, {%8,%9}, {%0,%1,%2,%3};"
        : "+f"(c[0]), "+f"(c[1]), "+f"(c[2]), "+f"(c[3])
        : "r"(a[0]), "r"(a[1]), "r"(a[2]), "r"(a[3]), "r"(b[0]), "r"(b[1]));
}
#define STS128(addr, v) \
    asm volatile("st.shared.v4.b32 [%0], {%1,%2,%3,%4};" \
        :: "r"((uint32_t)(addr)), "r"((v).x), "r"((v).y), "r"((v).z), "r"((v).w) : "memory")

// tile: rows of 64 halves = 128B = 8 x 16B units; SW128 XOR swizzle
#define TSWZ(r, c) ((uint32_t)(r) * 128u + ((((uint32_t)(c)) ^ ((uint32_t)(r) & 7u)) << 4))

// one k16 step: warp tile 64(M) x 32(N); 4 A-ldsm, 2 B-ldsm, 16 MMA
__device__ __forceinline__ void mma_step(uint32_t Ab, uint32_t Bb, int ks,
                                         const uint32_t* aoff, uint32_t ax,
                                         const uint32_t* boff, uint32_t bx, uint32_t cb,
                                         float acc[4][4][4]) {
    uint32_t a[4][4], b[2][4];
    const uint32_t cA = (uint32_t)(ks * 2) + cb;
#pragma unroll
    for (int mf = 0; mf < 4; mf++)
        ldsm4(a[mf][0], a[mf][1], a[mf][2], a[mf][3], Ab + aoff[mf] + ((cA ^ ax) << 4));
#pragma unroll
    for (int h = 0; h < 2; h++)
        ldsm4(b[h][0], b[h][1], b[h][2], b[h][3], Bb + boff[h] + ((cA ^ bx) << 4));
#pragma unroll
    for (int mf = 0; mf < 4; mf++)
#pragma unroll
        for (int nf = 0; nf < 4; nf++) {
            uint32_t bf[2] = { b[nf >> 1][nf & 1], b[nf >> 1][(nf & 1) + 2] };
            mma_f16(acc[mf][nf], a[mf], bf);
        }
}

// ---------------- 1. routing ------------------------------------------------
__global__ void route_kernel(const int* __restrict__ ids) {
    __shared__ int s_cnt[256][8];
    int tid = threadIdx.x;
    int local[8];
#pragma unroll
    for (int e = 0; e < 8; e++) local[e] = 0;
    int base = tid * 16;
#pragma unroll
    for (int i = 0; i < 16; i++) {
        int e = ids[base + i];
#pragma unroll
        for (int q = 0; q < 8; q++) if (q == e) local[q]++;
    }
#pragma unroll
    for (int e = 0; e < 8; e++) s_cnt[tid][e] = local[e];
    __syncthreads();
    if (tid < 8) {
        int acc = 0;
        for (int i = 0; i < 256; i++) {
            int v = s_cnt[i][tid];
            s_cnt[i][tid] = acc;
            acc += v;
        }
        d_cnt[tid] = acc;
    }
    __syncthreads();
    int run[8];
#pragma unroll
    for (int e = 0; e < 8; e++) run[e] = s_cnt[tid][e];
    for (int i = 0; i < 16; i++) {
        int idx = base + i;
        int e = ids[idx];
        int p = 0;
#pragma unroll
        for (int q = 0; q < 8; q++) if (q == e) p = run[q]++;
        d_pos[idx] = p;
        if (p < CAP) d_slot[e * CAP + p] = idx;
    }
}

// ---------------- 2. GEMM1 (fused gate/up + silu) ----------------------------
// 512 threads = 16 warps (2M x 8N). M=128, N=256 (gate 128 | up 128), BK=64.
#define G1_AT    16384u
#define G1_STAGE 49152u

__global__ __launch_bounds__(512, 1) void gemm1_kernel(const float* __restrict__ hidden,
                                                       const float* __restrict__ w1) {
    const int e = blockIdx.z, nt = blockIdx.y, mt = blockIdx.x;
    const int cnt = min(d_cnt[e], CAP);
    const int m0 = mt * 128;
    if (m0 >= cnt) return;

    extern __shared__ char smraw[];
    const uint32_t sb = smem_u32(smraw);

    const int tid = threadIdx.x, lane = tid & 31, warp = tid >> 5;
    const int wm = warp & 1, wn = warp >> 1;

    float acc[4][4][4];
#pragma unroll
    for (int mf = 0; mf < 4; mf++)
#pragma unroll
        for (int nf = 0; nf < 4; nf++)
#pragma unroll
            for (int q = 0; q < 4; q++) acc[mf][nf][q] = 0.f;

    // ldmatrix address precompute
    const uint32_t rA = wm * 64 + (lane & 15);
    const uint32_t rB = wn * 32 + (lane & 15);
    const uint32_t cb = lane >> 4;
    uint32_t aoff[4], boff[2];
#pragma unroll
    for (int mf = 0; mf < 4; mf++) aoff[mf] = (rA + mf * 16) * 128u;
    boff[0] = rB * 128u; boff[1] = (rB + 16) * 128u;
    const uint32_t ax = rA & 7, bx = rB & 7;

    // loaders: A: 2 units/thread; B: 4 units/thread
    const int ar = tid >> 2, ac0 = (tid & 3) * 2;
    const bool aval = (m0 + ar < cnt);
    const int atok = aval ? (d_slot[e * CAP + m0 + ar] >> 1) : 0;
    const float* aptr = hidden + (size_t)atok * H_DIM + ac0 * 8;
    uint32_t asts[2];
#pragma unroll
    for (int j = 0; j < 2; j++) asts[j] = TSWZ(ar, ac0 + j);

    const int br = tid >> 1, bc0 = (tid & 1) * 4;
    const int wrow = (br < 128) ? (nt * 128 + br) : (I_DIM + nt * 128 + (br - 128));
    const float* bptr = w1 + ((size_t)e * TWO_I + wrow) * H_DIM + bc0 * 8;
    uint32_t bsts[4];
#pragma unroll
    for (int j = 0; j < 4; j++) bsts[j] = G1_AT + TSWZ(br, bc0 + j);

    float4 ra[2][2], rb[2][2];

#define G1_LDG_A(kc) do {                                                        \
    _Pragma("unroll")                                                            \
    for (int j = 0; j < 2; j++) {                                                \
        ra[j][0] = aval ? *(const float4*)(aptr + (kc) + j * 8) : make_float4(0,0,0,0); \
        ra[j][1] = aval ? *(const float4*)(aptr + (kc) + j * 8 + 4) : make_float4(0,0,0,0); \
    } } while (0)
#define G1_STS_A(st) do {                                                        \
    _Pragma("unroll")                                                            \
    for (int j = 0; j < 2; j++) { uint4 u = pack8(ra[j][0], ra[j][1]);           \
        STS128(sb + (st) * G1_STAGE + asts[j], u); } } while (0)
#define G1_LDG_B(kc, jb) do {                                                    \
    _Pragma("unroll")                                                            \
    for (int j = 0; j < 2; j++) {                                                \
        rb[j][0] = *(const float4*)(bptr + (kc) + ((jb) + j) * 8);               \
        rb[j][1] = *(const float4*)(bptr + (kc) + ((jb) + j) * 8 + 4);           \
    } } while (0)
#define G1_STS_B(st, jb) do {                                                    \
    _Pragma("unroll")                                                            \
    for (int j = 0; j < 2; j++) { uint4 u = pack8(rb[j][0], rb[j][1]);           \
        STS128(sb + (st) * G1_STAGE + bsts[(jb) + j], u); } } while (0)

    // prologue: chunk 0 -> stage 0
    G1_LDG_A(0); G1_STS_A(0);
    G1_LDG_B(0, 0); G1_STS_B(0, 0);
    G1_LDG_B(0, 2); G1_STS_B(0, 2);
    __syncthreads();

    const int NC = H_DIM / BKH;  // 16
    for (int c = 0; c < NC; c++) {
        const int s = c & 1;
        const uint32_t Ab = sb + (uint32_t)s * G1_STAGE;
        const uint32_t Bb = Ab + G1_AT;
        const bool more = (c + 1 < NC);
        const int kn = (c + 1) * BKH;

        if (more) G1_LDG_B(kn, 0);
        mma_step(Ab, Bb, 0, aoff, ax, boff, bx, cb, acc);
        if (more) G1_STS_B(s ^ 1, 0);
        if (more) G1_LDG_B(kn, 2);
        mma_step(Ab, Bb, 1, aoff, ax, boff, bx, cb, acc);
        if (more) { G1_STS_B(s ^ 1, 2); G1_LDG_A(kn); }
        mma_step(Ab, Bb, 2, aoff, ax, boff, bx, cb, acc);
        if (more) G1_STS_A(s ^ 1);
        mma_step(Ab, Bb, 3, aoff, ax, boff, bx, cb, acc);
        __syncthreads();
    }

    // epilogue: up warps (wn>=4) stash acc in smem; gate warps apply silu, store fp16
    const int g = lane >> 2, tq = lane & 3;
    if (wn >= 4) {
        float* buf = (float*)smraw + ((size_t)((wn - 4) * 2 + wm)) * 2048;
#pragma unroll
        for (int mf = 0; mf < 4; mf++)
#pragma unroll
            for (int nf = 0; nf < 4; nf++) {
                int rl = (mf * 16 + g) * 32, rh = (mf * 16 + g + 8) * 32;
                int cc = nf * 8 + 2 * tq;
                buf[rl + cc]     = acc[mf][nf][0];
                buf[rl + cc + 1] = acc[mf][nf][1];
                buf[rh + cc]     = acc[mf][nf][2];
                buf[rh + cc + 1] = acc[mf][nf][3];
            }
    }
    __syncthreads();
    if (wn < 4) {
        const float* buf = (float*)smraw + ((size_t)(wn * 2 + wm)) * 2048;
#pragma unroll
        for (int mf = 0; mf < 4; mf++) {
            int mlo = m0 + wm * 64 + mf * 16 + g;
            int mhi = mlo + 8;
#pragma unroll
            for (int nf = 0; nf < 4; nf++) {
                int cc = nf * 8 + 2 * tq;
                int ic = nt * 128 + wn * 32 + cc;
                if (mlo < cnt) {
                    float g0 = acc[mf][nf][0], g1 = acc[mf][nf][1];
                    float u0 = buf[(mf * 16 + g) * 32 + cc];
                    float u1 = buf[(mf * 16 + g) * 32 + cc + 1];
                    float a0 = g0 * u0 / (1.f + __expf(-g0));
                    float a1 = g1 * u1 / (1.f + __expf(-g1));
                    *(uint32_t*)((__half*)d_act + ((size_t)e * CAP + mlo) * I_DIM + ic) = cvt2h(a0, a1);
                }
                if (mhi < cnt) {
                    float g0 = acc[mf][nf][2], g1 = acc[mf][nf][3];
                    float u0 = buf[(mf * 16 + g + 8) * 32 + cc];
                    float u1 = buf[(mf * 16 + g + 8) * 32 + cc + 1];
                    float a0 = g0 * u0 / (1.f + __expf(-g0));
                    float a1 = g1 * u1 / (1.f + __expf(-g1));
                    *(uint32_t*)((__half*)d_act + ((size_t)e * CAP + mhi) * I_DIM + ic) = cvt2h(a0, a1);
                }
            }
        }
    }
#undef G1_LDG_A
#undef G1_STS_A
#undef G1_LDG_B
#undef G1_STS_B
}

// ---------------- 3. GEMM2: y = act @ w2^T ----------------------------------
// 256 threads = 8 warps (2M x 4N). M=128, N=128, K=1408, BK=64.
#define G2_AT    16384u
#define G2_STAGE 32768u

__global__ __launch_bounds__(256, 2) void gemm2_kernel(const float* __restrict__ w2) {
    const int e = blockIdx.z, nt = blockIdx.y, mt = blockIdx.x;
    const int cnt = min(d_cnt[e], CAP);
    const int m0 = mt * 128;
    if (m0 >= cnt) return;

    extern __shared__ char smraw[];
    const uint32_t sb = smem_u32(smraw);

    const int tid = threadIdx.x, lane = tid & 31, warp = tid >> 5;
    const int wm = warp & 1, wn = warp >> 1;

    float acc[4][4][4];
#pragma unroll
    for (int mf = 0; mf < 4; mf++)
#pragma unroll
        for (int nf = 0; nf < 4; nf++)
#pragma unroll
            for (int q = 0; q < 4; q++) acc[mf][nf][q] = 0.f;

    const uint32_t rA = wm * 64 + (lane & 15);
    const uint32_t rB = wn * 32 + (lane & 15);
    const uint32_t cb = lane >> 4;
    uint32_t aoff[4], boff[2];
#pragma unroll
    for (int mf = 0; mf < 4; mf++) aoff[mf] = (rA + mf * 16) * 128u;
    boff[0] = rB * 128u; boff[1] = (rB + 16) * 128u;
    const uint32_t ax = rA & 7, bx = rB & 7;

    // loaders: both A and B: r = tid>>1 (0..127), 4 units each
    const int lr = tid >> 1, lc0 = (tid & 1) * 4;
    const __half* aptr = d_act + ((size_t)e * CAP + m0 + lr) * I_DIM + lc0 * 8;
    const float*  bptr = w2 + ((size_t)e * H_DIM + nt * 128 + lr) * I_DIM + lc0 * 8;
    uint32_t asts[4], bsts[4];
#pragma unroll
    for (int j = 0; j < 4; j++) {
        asts[j] = TSWZ(lr, lc0 + j);
        bsts[j] = G2_AT + TSWZ(lr, lc0 + j);
    }

    uint4 rau[4];
    float4 rbf[2][2];

#define G2_LDG_A(kc) do {                                                        \
    _Pragma("unroll")                                                            \
    for (int j = 0; j < 4; j++) rau[j] = *(const uint4*)(aptr + (kc) + j * 8);   \
} while (0)
#define G2_STS_A(st) do {                                                        \
    _Pragma("unroll")                                                            \
    for (int j = 0; j < 4; j++) STS128(sb + (st) * G2_STAGE + asts[j], rau[j]);  \
} while (0)
#define G2_LDG_B(kc, jb) do {                                                    \
    _Pragma("unroll")                                                            \
    for (int j = 0; j < 2; j++) {                                                \
        rbf[j][0] = *(const float4*)(bptr + (kc) + ((jb) + j) * 8);              \
        rbf[j][1] = *(const float4*)(bptr + (kc) + ((jb) + j) * 8 + 4);          \
    } } while (0)
#define G2_STS_B(st, jb) do {                                                    \
    _Pragma("unroll")                                                            \
    for (int j = 0; j < 2; j++) { uint4 u = pack8(rbf[j][0], rbf[j][1]);         \
        STS128(sb + (st) * G2_STAGE + bsts[(jb) + j], u); } } while (0)

    G2_LDG_A(0); G2_STS_A(0);
    G2_LDG_B(0, 0); G2_STS_B(0, 0);
    G2_LDG_B(0, 2); G2_STS_B(0, 2);
    __syncthreads();

    const int NC = I_DIM / BKH;  // 22
    for (int c = 0; c < NC; c++) {
        const int s = c & 1;
        const uint32_t Ab = sb + (uint32_t)s * G2_STAGE;
        const uint32_t Bb = Ab + G2_AT;
        const bool more = (c + 1 < NC);
        const int kn = (c + 1) * BKH;

        if (more) G2_LDG_B(kn, 0);
        mma_step(Ab, Bb, 0, aoff, ax, boff, bx, cb, acc);
        if (more) G2_STS_B(s ^ 1, 0);
        if (more) G2_LDG_B(kn, 2);
        mma_step(Ab, Bb, 1, aoff, ax, boff, bx, cb, acc);
        if (more) { G2_STS_B(s ^ 1, 2); G2_LDG_A(kn); }
        mma_step(Ab, Bb, 2, aoff, ax, boff, bx, cb, acc);
        if (more) G2_STS_A(s ^ 1);
        mma_step(Ab, Bb, 3, aoff, ax, boff, bx, cb, acc);
        __syncthreads();
    }

    const int g = lane >> 2, tq = lane & 3;
#pragma unroll
    for (int mf = 0; mf < 4; mf++) {
        int mlo = m0 + wm * 64 + mf * 16 + g;
        int mhi = mlo + 8;
#pragma unroll
        for (int nf = 0; nf < 4; nf++) {
            int col = nt * 128 + wn * 32 + nf * 8 + 2 * tq;
            if (mlo < cnt) {
                float* dst = d_y + ((size_t)e * CAP + mlo) * H_DIM + col;
                dst[0] = acc[mf][nf][0];
                dst[1] = acc[mf][nf][1];
            }
            if (mhi < cnt) {
                float* dst = d_y + ((size_t)e * CAP + mhi) * H_DIM + col;
                dst[0] = acc[mf][nf][2];
                dst[1] = acc[mf][nf][3];
            }
        }
    }
#undef G2_LDG_A
#undef G2_STS_A
#undef G2_LDG_B
#undef G2_STS_B
}

// ---------------- 4. combine ------------------------------------------------
__global__ void combine_kernel(const float* __restrict__ tw,
                               const int* __restrict__ ids,
                               float* __restrict__ out) {
    int tok = blockIdx.x;
    int e0 = ids[tok * 2 + 0], e1 = ids[tok * 2 + 1];
    int p0 = d_pos[tok * 2 + 0], p1 = d_pos[tok * 2 + 1];
    float w0 = tw[tok * 2 + 0], w1v = tw[tok * 2 + 1];
    bool k0 = (p0 < CAP), k1 = (p1 < CAP);

    int c = threadIdx.x;
    float4 r = make_float4(0.f, 0.f, 0.f, 0.f);
    if (k0) {
        float4 v = *(const float4*)(d_y + ((size_t)e0 * CAP + p0) * H_DIM + c * 4);
        r.x += w0 * v.x; r.y += w0 * v.y; r.z += w0 * v.z; r.w += w0 * v.w;
    }
    if (k1) {
        float4 v = *(const float4*)(d_y + ((size_t)e1 * CAP + p1) * H_DIM + c * 4);
        r.x += w1v * v.x; r.y += w1v * v.y; r.z += w1v * v.z; r.w += w1v * v.w;
    }
    *(float4*)(out + (size_t)tok * H_DIM + c * 4) = r;
}

// ---------------- launch -----------------------------------------------------
extern "C" void kernel_launch(void* const* d_in, const int* in_sizes, int n_in,
                              void* d_out, int out_size) {
    const float* hidden = (const float*)d_in[0];
    const float* w1     = (const float*)d_in[1];
    const float* w2     = (const float*)d_in[2];
    const float* tw     = (const float*)d_in[3];
    const int*   ids    = (const int*)d_in[4];
    float* out = (float*)d_out;

    const int g1_smem = 2 * (int)G1_STAGE;  // 98304
    const int g2_smem = 2 * (int)G2_STAGE;  // 65536
    cudaFuncSetAttribute(gemm1_kernel, cudaFuncAttributeMaxDynamicSharedMemorySize, g1_smem);
    cudaFuncSetAttribute(gemm2_kernel, cudaFuncAttributeMaxDynamicSharedMemorySize, g2_smem);

    route_kernel<<<1, 256>>>(ids);
    gemm1_kernel<<<dim3(CAP / 128, I_DIM / 128, E_DIM), 512, g1_smem>>>(hidden, w1);
    gemm2_kernel<<<dim3(CAP / 128, H_DIM / 128, E_DIM), 256, g2_smem>>>(w2);
    combine_kernel<<<T_DIM, 256>>>(tw, ids, out);
}